// round 2
// baseline (speedup 1.0000x reference)
#include <cuda_runtime.h>

#define BATCH 8
#define NPTS  4096
#define KNN   32
#define DIM   64
#define CIN   67
#define PH    128   // hidden width of resnet
#define EPSF  1e-5f

// ---------------- scratch (static device arrays; no allocs allowed) ----------------
__device__ __align__(256) float  d_FG[BATCH * NPTS * DIM];   // 8 MB: (F+G)[b,n,o]
__device__ __align__(256) float4 d_xyzw[BATCH * NPTS];       // x,y,z,|x|^2
__device__ __align__(256) float  d_newp[BATCH * NPTS * DIM]; // 8 MB: [b,n,o] (n-major)

// ============================================================================
// k1: FG[b,n,o] = sum_{c<64} points[b,c,n]*W[o,c] + sum_{j<3} xyz[b,j,n]*W[o,64+j]
//     also packs xyzw with reference-faithful |x|^2 rounding.
// ============================================================================
__global__ __launch_bounds__(64) void k1_fg(const float* __restrict__ xyz,
                                            const float* __restrict__ points,
                                            const float* __restrict__ W) {
    __shared__ float Wsh[64][68];    // padded rows (272B, 16B-aligned)
    __shared__ float outsh[64][65];  // padded to avoid bank conflicts
    const int tid = threadIdx.x;

    for (int i = tid; i < 64 * CIN; i += 64) Wsh[i / CIN][i % CIN] = W[i];
    __syncthreads();

    const int pt = blockIdx.x * 64 + tid;       // 0..32767
    const int b = pt >> 12;
    const int n = pt & (NPTS - 1);

    float in[CIN];
    {
        const float* pb = points + ((size_t)b * DIM) * NPTS + n;
#pragma unroll
        for (int c = 0; c < 64; c++) in[c] = pb[(size_t)c * NPTS];
        const float* xb = xyz + ((size_t)b * 3) * NPTS + n;
        float x = xb[0], y = xb[NPTS], z = xb[2 * NPTS];
        in[64] = x; in[65] = y; in[66] = z;
        // sq = (x*x + y*y) + z*z with explicit fp32 rounding (matches XLA reduce)
        float sq = __fadd_rn(__fadd_rn(__fmul_rn(x, x), __fmul_rn(y, y)), __fmul_rn(z, z));
        d_xyzw[pt] = make_float4(x, y, z, sq);
    }

    for (int o = 0; o < 64; o++) {
        const float4* wrow = (const float4*)&Wsh[o][0];
        float acc = 0.f;
#pragma unroll
        for (int q = 0; q < 16; q++) {
            float4 w4 = wrow[q];
            acc = fmaf(in[4 * q + 0], w4.x, acc);
            acc = fmaf(in[4 * q + 1], w4.y, acc);
            acc = fmaf(in[4 * q + 2], w4.z, acc);
            acc = fmaf(in[4 * q + 3], w4.w, acc);
        }
        acc = fmaf(in[64], Wsh[o][64], acc);
        acc = fmaf(in[65], Wsh[o][65], acc);
        acc = fmaf(in[66], Wsh[o][66], acc);
        outsh[tid][o] = acc;
    }
    __syncthreads();

    // coalesced store of the 64x64 tile
    float* dst = d_FG + (size_t)blockIdx.x * (64 * 64);
    for (int i = tid; i < 64 * 64; i += 64) dst[i] = outsh[i >> 6][i & 63];
}

// ============================================================================
// k2: warp per query point.
//   Phase 1: ascending-index scan, collect first up-to-32 indices with
//            dist = (sq_n + sq_m) - 2*dot <= r^2  (reference rounding).
//   Phase 2: gather FG rows of those neighbors, running max/min per channel.
//   Epilogue: y[o] = relu(s_o*(E_o - G[n,o]) + C_o), E = max (s>=0) or min (s<0)
//             C_o = s_o*(b_conv - rm) + bt. Writes newp [B,N,64].
// ============================================================================
__global__ __launch_bounds__(256) void k2_ball(const float* __restrict__ W,
                                               const float* __restrict__ bconv,
                                               const float* __restrict__ g,
                                               const float* __restrict__ bt,
                                               const float* __restrict__ rm,
                                               const float* __restrict__ rv) {
    __shared__ int idxbuf[8][KNN];
    const int lane = threadIdx.x & 31;
    const int w    = threadIdx.x >> 5;
    const int gw   = blockIdx.x * 8 + w;       // global query point id
    const int b    = gw >> 12;

    const float4 q = d_xyzw[gw];
    const float r2 = 0.04f;                    // fp32(0.2*0.2), matches jnp promotion
    int* buf = idxbuf[w];
    int count = 0;

    const float4* xb = d_xyzw + ((size_t)b << 12);
    for (int base = 0; base < NPTS; base += 32) {
        const int m = base + lane;
        float4 p = xb[m];
        float dot  = fmaf(q.z, p.z, fmaf(q.y, p.y, __fmul_rn(q.x, p.x)));
        float dist = __fsub_rn(__fadd_rn(q.w, p.w), __fmul_rn(2.0f, dot));
        unsigned mask = __ballot_sync(0xffffffffu, !(dist > r2));
        int pos = count + __popc(mask & ((1u << lane) - 1u));
        if ((mask >> lane) & 1u) {
            if (pos < KNN) buf[pos] = m;
        }
        count += __popc(mask);
        if (count >= KNN) break;
    }
    __syncwarp();
    if (count > KNN) count = KNN;

    const float* FGb = d_FG + (((size_t)b << 12) * 64);
    float mx0 = -3.4e38f, mx1 = -3.4e38f, mn0 = 3.4e38f, mn1 = 3.4e38f;

    int k = 0;
    for (; k + 4 <= count; k += 4) {   // 4 outstanding gathers for MLP
        int i0 = buf[k], i1 = buf[k + 1], i2 = buf[k + 2], i3 = buf[k + 3];
        float2 v0 = *(const float2*)(FGb + (size_t)i0 * 64 + 2 * lane);
        float2 v1 = *(const float2*)(FGb + (size_t)i1 * 64 + 2 * lane);
        float2 v2 = *(const float2*)(FGb + (size_t)i2 * 64 + 2 * lane);
        float2 v3 = *(const float2*)(FGb + (size_t)i3 * 64 + 2 * lane);
        mx0 = fmaxf(mx0, fmaxf(fmaxf(v0.x, v1.x), fmaxf(v2.x, v3.x)));
        mx1 = fmaxf(mx1, fmaxf(fmaxf(v0.y, v1.y), fmaxf(v2.y, v3.y)));
        mn0 = fminf(mn0, fminf(fminf(v0.x, v1.x), fminf(v2.x, v3.x)));
        mn1 = fminf(mn1, fminf(fminf(v0.y, v1.y), fminf(v2.y, v3.y)));
    }
    for (; k < count; k++) {
        int i0 = buf[k];
        float2 v0 = *(const float2*)(FGb + (size_t)i0 * 64 + 2 * lane);
        mx0 = fmaxf(mx0, v0.x); mx1 = fmaxf(mx1, v0.y);
        mn0 = fminf(mn0, v0.x); mn1 = fminf(mn1, v0.y);
    }

    // epilogue: 2 channels per lane
    const int c0 = 2 * lane, c1 = c0 + 1;
    float G0 = fmaf(q.z, W[c0 * CIN + 66], fmaf(q.y, W[c0 * CIN + 65], __fmul_rn(q.x, W[c0 * CIN + 64])));
    float G1 = fmaf(q.z, W[c1 * CIN + 66], fmaf(q.y, W[c1 * CIN + 65], __fmul_rn(q.x, W[c1 * CIN + 64])));
    float s0 = g[c0] * rsqrtf(rv[c0] + EPSF);
    float s1 = g[c1] * rsqrtf(rv[c1] + EPSF);
    float C0 = fmaf(s0, bconv[c0] - rm[c0], bt[c0]);
    float C1 = fmaf(s1, bconv[c1] - rm[c1], bt[c1]);
    float E0 = (s0 >= 0.f) ? mx0 : mn0;
    float E1 = (s1 >= 0.f) ? mx1 : mn1;
    float y0 = fmaxf(0.f, fmaf(s0, E0 - G0, C0));
    float y1 = fmaxf(0.f, fmaf(s1, E1 - G1, C1));
    *(float2*)(d_newp + (size_t)gw * 64 + c0) = make_float2(y0, y1);
}

// ============================================================================
// k3: fused pointwise resnet. Thread = one point.
//   x1 = relu(A1 * (W1 @ np) + C1);  x2a = A2 * (W2 @ x1) + C2
//   out[b,c,n] = relu(x2a + points[b,c,n])
// ============================================================================
__global__ __launch_bounds__(128) void k3_resnet(const float* __restrict__ W1,
                                                 const float* __restrict__ b1,
                                                 const float* __restrict__ g1,
                                                 const float* __restrict__ bt1,
                                                 const float* __restrict__ rm1,
                                                 const float* __restrict__ rv1,
                                                 const float* __restrict__ W2,
                                                 const float* __restrict__ b2,
                                                 const float* __restrict__ g2,
                                                 const float* __restrict__ bt2,
                                                 const float* __restrict__ rm2,
                                                 const float* __restrict__ rv2,
                                                 const float* __restrict__ points,
                                                 float* __restrict__ out) {
    extern __shared__ float sm[];
    float* W1sh  = sm;                    // [128][64]
    float* W2Tsh = W1sh + PH * 64;        // [128][64] = W2^T
    float* A1 = W2Tsh + PH * 64;          // 128
    float* C1 = A1 + PH;                  // 128
    float* A2 = C1 + PH;                  // 64
    float* C2 = A2 + 64;                  // 64
    const int tid = threadIdx.x;

    for (int i = tid; i < PH * 64; i += 128) W1sh[i] = W1[i];
    for (int i = tid; i < 64 * PH; i += 128) W2Tsh[(i & (PH - 1)) * 64 + (i >> 7)] = W2[i];
    if (tid < PH) {
        float s = g1[tid] * rsqrtf(rv1[tid] + EPSF);
        A1[tid] = s;
        C1[tid] = fmaf(s, b1[tid] - rm1[tid], bt1[tid]);
    }
    if (tid < 64) {
        float s = g2[tid] * rsqrtf(rv2[tid] + EPSF);
        A2[tid] = s;
        C2[tid] = fmaf(s, b2[tid] - rm2[tid], bt2[tid]);
    }
    __syncthreads();

    const int pt = blockIdx.x * 128 + tid;
    float np[64];
    {
        const float4* src = (const float4*)(d_newp + (size_t)pt * 64);
#pragma unroll
        for (int qq = 0; qq < 16; qq++) {
            float4 v = src[qq];
            np[4 * qq] = v.x; np[4 * qq + 1] = v.y; np[4 * qq + 2] = v.z; np[4 * qq + 3] = v.w;
        }
    }
    float acc2[64];
#pragma unroll
    for (int c = 0; c < 64; c++) acc2[c] = 0.f;

    for (int p = 0; p < PH; p++) {
        const float4* w1r = (const float4*)(W1sh + p * 64);
        float a = 0.f;
#pragma unroll
        for (int qq = 0; qq < 16; qq++) {
            float4 w4 = w1r[qq];
            a = fmaf(np[4 * qq + 0], w4.x, a);
            a = fmaf(np[4 * qq + 1], w4.y, a);
            a = fmaf(np[4 * qq + 2], w4.z, a);
            a = fmaf(np[4 * qq + 3], w4.w, a);
        }
        float x1 = fmaxf(0.f, fmaf(A1[p], a, C1[p]));
        const float4* w2r = (const float4*)(W2Tsh + p * 64);
#pragma unroll
        for (int qq = 0; qq < 16; qq++) {
            float4 w4 = w2r[qq];
            acc2[4 * qq + 0] = fmaf(x1, w4.x, acc2[4 * qq + 0]);
            acc2[4 * qq + 1] = fmaf(x1, w4.y, acc2[4 * qq + 1]);
            acc2[4 * qq + 2] = fmaf(x1, w4.z, acc2[4 * qq + 2]);
            acc2[4 * qq + 3] = fmaf(x1, w4.w, acc2[4 * qq + 3]);
        }
    }

    const int b = pt >> 12;
    const int n = pt & (NPTS - 1);
    const float* pin = points + ((size_t)b * 64) * NPTS + n;
    float* pout = out + (size_t)BATCH * 3 * NPTS + ((size_t)b * 64) * NPTS + n;
#pragma unroll
    for (int c = 0; c < 64; c++) {
        float y = fmaf(A2[c], acc2[c], C2[c]) + pin[(size_t)c * NPTS];
        pout[(size_t)c * NPTS] = fmaxf(0.f, y);
    }
}

// ============================================================================
extern "C" void kernel_launch(void* const* d_in, const int* in_sizes, int n_in,
                              void* d_out, int out_size) {
    const float* xyz    = (const float*)d_in[0];
    const float* points = (const float*)d_in[1];
    const float* W      = (const float*)d_in[2];
    const float* bconv  = (const float*)d_in[3];
    const float* g      = (const float*)d_in[4];
    const float* bt     = (const float*)d_in[5];
    const float* rm     = (const float*)d_in[6];
    const float* rv     = (const float*)d_in[7];
    const float* W1     = (const float*)d_in[8];
    const float* b1     = (const float*)d_in[9];
    const float* g1     = (const float*)d_in[10];
    const float* bt1    = (const float*)d_in[11];
    const float* rm1    = (const float*)d_in[12];
    const float* rv1    = (const float*)d_in[13];
    const float* W2     = (const float*)d_in[14];
    const float* b2     = (const float*)d_in[15];
    const float* g2     = (const float*)d_in[16];
    const float* bt2    = (const float*)d_in[17];
    const float* rm2    = (const float*)d_in[18];
    const float* rv2    = (const float*)d_in[19];
    float* out = (float*)d_out;

    // passthrough xyz (first element of the returned tuple)
    cudaMemcpyAsync(out, xyz, (size_t)BATCH * 3 * NPTS * sizeof(float),
                    cudaMemcpyDeviceToDevice, 0);

    k1_fg<<<(BATCH * NPTS) / 64, 64>>>(xyz, points, W);
    k2_ball<<<(BATCH * NPTS) / 8, 256>>>(W, bconv, g, bt, rm, rv);

    const int k3_smem = (PH * 64 * 2 + PH * 2 + 64 * 2) * (int)sizeof(float);
    cudaFuncSetAttribute(k3_resnet, cudaFuncAttributeMaxDynamicSharedMemorySize, k3_smem);
    k3_resnet<<<(BATCH * NPTS) / 128, 128, k3_smem>>>(W1, b1, g1, bt1, rm1, rv1,
                                                      W2, b2, g2, bt2, rm2, rv2,
                                                      points, out);
    (void)in_sizes; (void)n_in; (void)out_size;
}

// round 4
// speedup vs baseline: 1.0616x; 1.0616x over previous
#include <cuda_runtime.h>

#define BATCH 8
#define NPTS  4096
#define KNN   32
#define DIM   64
#define CIN   67
#define PH    128
#define EPSF  1e-5f

// ---------------- static device scratch (no allocs allowed) ----------------
__device__ __align__(256) float  d_FG[BATCH * NPTS * DIM];    // 8 MB
__device__ __align__(256) float4 d_xyzw[BATCH * NPTS];        // 512 KB
__device__ __align__(256) float  d_newp[BATCH * NPTS * DIM];  // 8 MB  [pt][c]
__device__ __align__(256) float  d_H[BATCH * NPTS * PH];      // 16 MB [pt][o]

// ============================================================================
// k1: FG[pt][o] = sum_{c<64} points[b,c,n]*W[o,c] + sum_{j<3} xyz[b,j,n]*W[o,64+j]
// 256 threads = 64 points x 4 output-quarters (16 outputs per thread).
// ============================================================================
__global__ __launch_bounds__(256) void k1_fg(const float* __restrict__ xyz,
                                             const float* __restrict__ points,
                                             const float* __restrict__ W) {
    __shared__ float Wsh[64][68];
    const int tid = threadIdx.x;
    const int p   = tid & 63;        // point within block
    const int g   = tid >> 6;        // output quarter 0..3

    for (int i = tid; i < 64 * CIN; i += 256) Wsh[i / CIN][i % CIN] = W[i];
    __syncthreads();

    const int pt = blockIdx.x * 64 + p;
    const int b  = pt >> 12;
    const int n  = pt & (NPTS - 1);

    float in[CIN];
    {
        const float* pb = points + ((size_t)b * DIM) * NPTS + n;
#pragma unroll
        for (int c = 0; c < 64; c++) in[c] = pb[(size_t)c * NPTS];
        const float* xb = xyz + ((size_t)b * 3) * NPTS + n;
        float x = xb[0], y = xb[NPTS], z = xb[2 * NPTS];
        in[64] = x; in[65] = y; in[66] = z;
        if (g == 0) {
            float sq = __fadd_rn(__fadd_rn(__fmul_rn(x, x), __fmul_rn(y, y)), __fmul_rn(z, z));
            d_xyzw[pt] = make_float4(x, y, z, sq);
        }
    }

    const int o0 = 16 * g;
    float out16[16];
#pragma unroll
    for (int oo = 0; oo < 16; oo++) {
        const int o = o0 + oo;
        const float4* wrow = (const float4*)&Wsh[o][0];
        float acc = 0.f;
#pragma unroll
        for (int q = 0; q < 16; q++) {
            float4 w4 = wrow[q];
            acc = fmaf(in[4 * q + 0], w4.x, acc);
            acc = fmaf(in[4 * q + 1], w4.y, acc);
            acc = fmaf(in[4 * q + 2], w4.z, acc);
            acc = fmaf(in[4 * q + 3], w4.w, acc);
        }
        acc = fmaf(in[64], Wsh[o][64], acc);
        acc = fmaf(in[65], Wsh[o][65], acc);
        acc = fmaf(in[66], Wsh[o][66], acc);
        out16[oo] = acc;
    }
    float* dst = d_FG + (size_t)pt * 64 + o0;
#pragma unroll
    for (int s = 0; s < 4; s++)
        *(float4*)(dst + 4 * s) = make_float4(out16[4 * s], out16[4 * s + 1],
                                              out16[4 * s + 2], out16[4 * s + 3]);
}

// ============================================================================
// k2: warp per query. Scan 64 points/iter with early exit at 32 hits.
// Pad index list to 32 with buf[0] (== reference's pad-with-first; dup rows
// are no-ops for max/min). Fixed 16x LDG.128 gather, half-warp per row.
// ============================================================================
__global__ __launch_bounds__(64) void k2_ball(const float* __restrict__ W,
                                              const float* __restrict__ bconv,
                                              const float* __restrict__ g,
                                              const float* __restrict__ bt,
                                              const float* __restrict__ rm,
                                              const float* __restrict__ rv) {
    __shared__ int idxbuf[2][KNN];
    const int lane = threadIdx.x & 31;
    const int w    = threadIdx.x >> 5;
    const int gw   = blockIdx.x * 2 + w;
    const int b    = gw >> 12;

    const float4 q = d_xyzw[gw];
    int* buf = idxbuf[w];
    int count = 0;
    const float4* xb = d_xyzw + ((size_t)b << 12);
    const unsigned ltmask = (1u << lane) - 1u;

    for (int base = 0; base < NPTS; base += 64) {
        float4 p0 = xb[base + lane];
        float4 p1 = xb[base + 32 + lane];
        float dot0 = fmaf(q.z, p0.z, fmaf(q.y, p0.y, __fmul_rn(q.x, p0.x)));
        float d0   = __fsub_rn(__fadd_rn(q.w, p0.w), __fmul_rn(2.0f, dot0));
        float dot1 = fmaf(q.z, p1.z, fmaf(q.y, p1.y, __fmul_rn(q.x, p1.x)));
        float d1   = __fsub_rn(__fadd_rn(q.w, p1.w), __fmul_rn(2.0f, dot1));
        unsigned m0 = __ballot_sync(0xffffffffu, !(d0 > 0.04f));
        unsigned m1 = __ballot_sync(0xffffffffu, !(d1 > 0.04f));
        int c0 = __popc(m0);
        int pos0 = count + __popc(m0 & ltmask);
        if ((m0 >> lane) & 1u) { if (pos0 < KNN) buf[pos0] = base + lane; }
        int pos1 = count + c0 + __popc(m1 & ltmask);
        if ((m1 >> lane) & 1u) { if (pos1 < KNN) buf[pos1] = base + 32 + lane; }
        count += c0 + __popc(m1);
        if (count >= KNN) break;
    }
    __syncwarp();
    int cnt = min(count, KNN);
    if (lane >= cnt) buf[lane] = buf[0];
    __syncwarp();

    // gather: half-warp h handles rows 2k+h; lane j owns channels 4j..4j+3
    const int h = lane >> 4, j = lane & 15;
    const float* rowbase = d_FG + (((size_t)b << 12) * 64) + 4 * j;
    float mx[4] = {-3.4e38f, -3.4e38f, -3.4e38f, -3.4e38f};
    float mn[4] = { 3.4e38f,  3.4e38f,  3.4e38f,  3.4e38f};
#pragma unroll
    for (int k = 0; k < 16; k++) {
        int i = buf[2 * k + h];
        float4 v = *(const float4*)(rowbase + (size_t)i * 64);
        mx[0] = fmaxf(mx[0], v.x); mn[0] = fminf(mn[0], v.x);
        mx[1] = fmaxf(mx[1], v.y); mn[1] = fminf(mn[1], v.y);
        mx[2] = fmaxf(mx[2], v.z); mn[2] = fminf(mn[2], v.z);
        mx[3] = fmaxf(mx[3], v.w); mn[3] = fminf(mn[3], v.w);
    }
#pragma unroll
    for (int u = 0; u < 4; u++) {
        mx[u] = fmaxf(mx[u], __shfl_xor_sync(0xffffffffu, mx[u], 16));
        mn[u] = fminf(mn[u], __shfl_xor_sync(0xffffffffu, mn[u], 16));
    }

    if (h == 0) {
        const int c = 4 * j;
        float y[4];
#pragma unroll
        for (int u = 0; u < 4; u++) {
            const int cu = c + u;
            float w64 = __ldg(&W[cu * CIN + 64]);
            float w65 = __ldg(&W[cu * CIN + 65]);
            float w66 = __ldg(&W[cu * CIN + 66]);
            float G = fmaf(q.z, w66, fmaf(q.y, w65, __fmul_rn(q.x, w64)));
            float s = __ldg(&g[cu]) * rsqrtf(__ldg(&rv[cu]) + EPSF);
            float C = fmaf(s, __ldg(&bconv[cu]) - __ldg(&rm[cu]), __ldg(&bt[cu]));
            float E = (s >= 0.f) ? mx[u] : mn[u];
            y[u] = fmaxf(0.f, fmaf(s, E - G, C));
        }
        *(float4*)(d_newp + (size_t)gw * 64 + c) = make_float4(y[0], y[1], y[2], y[3]);
    }
}

// ============================================================================
// k3a: H[pt][o] = relu(A1[o]*(np[pt]@W1[o]) + C1[o]).  64 pts x 128 o per
// block, 256 threads, 4x8 register tiles.
// ============================================================================
#define XP  68
#define WP1 132
__global__ __launch_bounds__(256) void k3a(const float* __restrict__ W1,
                                           const float* __restrict__ b1,
                                           const float* __restrict__ g1,
                                           const float* __restrict__ bt1,
                                           const float* __restrict__ rm1,
                                           const float* __restrict__ rv1) {
    extern __shared__ float sm[];
    float* Xs    = sm;                    // [64 c][XP]
    float* W1Ts  = Xs + 64 * XP;          // [64 c][WP1]
    float* A1    = W1Ts + 64 * WP1;       // [128]
    float* C1    = A1 + PH;               // [128]
    const int tid = threadIdx.x;
    const int base = blockIdx.x * 64;

    for (int t = tid; t < 64 * 16; t += 256) {         // np tile, transposed
        int p = t >> 4, qc = t & 15;
        float4 v = *(const float4*)(d_newp + (size_t)(base + p) * 64 + 4 * qc);
        Xs[(4 * qc + 0) * XP + p] = v.x;
        Xs[(4 * qc + 1) * XP + p] = v.y;
        Xs[(4 * qc + 2) * XP + p] = v.z;
        Xs[(4 * qc + 3) * XP + p] = v.w;
    }
    for (int t = tid; t < PH * 64; t += 256) {         // W1 [o][c] -> [c][o]
        int o = t >> 6, c = t & 63;
        W1Ts[c * WP1 + o] = W1[t];
    }
    if (tid < PH) {
        float s = g1[tid] * rsqrtf(rv1[tid] + EPSF);
        A1[tid] = s;
        C1[tid] = fmaf(s, b1[tid] - rm1[tid], bt1[tid]);
    }
    __syncthreads();

    const int to = tid & 15;      // o-group: 8 outputs 8*to..
    const int tp = tid >> 4;      // p-group: 4 points 4*tp..
    float acc[4][8];
#pragma unroll
    for (int i = 0; i < 4; i++)
#pragma unroll
        for (int jj = 0; jj < 8; jj++) acc[i][jj] = 0.f;

#pragma unroll 4
    for (int c = 0; c < 64; c++) {
        float4 x  = *(const float4*)&Xs[c * XP + 4 * tp];
        float4 wa = *(const float4*)&W1Ts[c * WP1 + 8 * to];
        float4 wb = *(const float4*)&W1Ts[c * WP1 + 8 * to + 4];
        float xv[4] = {x.x, x.y, x.z, x.w};
        float wv[8] = {wa.x, wa.y, wa.z, wa.w, wb.x, wb.y, wb.z, wb.w};
#pragma unroll
        for (int i = 0; i < 4; i++)
#pragma unroll
            for (int jj = 0; jj < 8; jj++)
                acc[i][jj] = fmaf(xv[i], wv[jj], acc[i][jj]);
    }

#pragma unroll
    for (int i = 0; i < 4; i++) {
        const int p = base + 4 * tp + i;
        float hval[8];
#pragma unroll
        for (int jj = 0; jj < 8; jj++) {
            int o = 8 * to + jj;
            hval[jj] = fmaxf(0.f, fmaf(A1[o], acc[i][jj], C1[o]));
        }
        float* dst = d_H + (size_t)p * PH + 8 * to;
        *(float4*)(dst)     = make_float4(hval[0], hval[1], hval[2], hval[3]);
        *(float4*)(dst + 4) = make_float4(hval[4], hval[5], hval[6], hval[7]);
    }
}

// ============================================================================
// k3b: out[b,d,n] = relu(A2[d]*(H[pt]@W2[d]) + C2[d] + points[b,d,n]).
// 64 pts x 64 d per block, 256 threads, 4x4 register tiles.
// ============================================================================
#define HP  68
#define WP2 68
__global__ __launch_bounds__(256) void k3b(const float* __restrict__ W2,
                                           const float* __restrict__ b2,
                                           const float* __restrict__ g2,
                                           const float* __restrict__ bt2,
                                           const float* __restrict__ rm2,
                                           const float* __restrict__ rv2,
                                           const float* __restrict__ points,
                                           float* __restrict__ out) {
    extern __shared__ float sm[];
    float* Hs   = sm;                     // [128 o][HP]
    float* W2Ts = Hs + PH * HP;           // [128 o][WP2]
    float* A2   = W2Ts + PH * WP2;        // [64]
    float* C2   = A2 + 64;                // [64]
    const int tid = threadIdx.x;
    const int base = blockIdx.x * 64;

    for (int t = tid; t < 64 * 32; t += 256) {         // H tile, transposed
        int p = t >> 5, qo = t & 31;
        float4 v = *(const float4*)(d_H + (size_t)(base + p) * PH + 4 * qo);
        Hs[(4 * qo + 0) * HP + p] = v.x;
        Hs[(4 * qo + 1) * HP + p] = v.y;
        Hs[(4 * qo + 2) * HP + p] = v.z;
        Hs[(4 * qo + 3) * HP + p] = v.w;
    }
    for (int t = tid; t < 64 * PH; t += 256) {         // W2 [d][o] -> [o][d]
        int d = t >> 7, o = t & 127;
        W2Ts[o * WP2 + d] = W2[t];
    }
    if (tid < 64) {
        float s = g2[tid] * rsqrtf(rv2[tid] + EPSF);
        A2[tid] = s;
        C2[tid] = fmaf(s, b2[tid] - rm2[tid], bt2[tid]);
    }
    __syncthreads();

    const int to = tid & 15;      // d-group: 4 outputs 4*to..
    const int tp = tid >> 4;      // p-group: 4 points 4*tp..
    float acc[4][4];
#pragma unroll
    for (int i = 0; i < 4; i++)
#pragma unroll
        for (int jj = 0; jj < 4; jj++) acc[i][jj] = 0.f;

#pragma unroll 8
    for (int o = 0; o < PH; o++) {
        float4 x = *(const float4*)&Hs[o * HP + 4 * tp];
        float4 ww = *(const float4*)&W2Ts[o * WP2 + 4 * to];
        float xv[4] = {x.x, x.y, x.z, x.w};
        float wv[4] = {ww.x, ww.y, ww.z, ww.w};
#pragma unroll
        for (int i = 0; i < 4; i++)
#pragma unroll
            for (int jj = 0; jj < 4; jj++)
                acc[i][jj] = fmaf(xv[i], wv[jj], acc[i][jj]);
    }

    const int b  = base >> 12;
    const int n0 = (base & (NPTS - 1)) + 4 * tp;
    const float* pin = points + ((size_t)b * 64) * NPTS + n0;
    float* pout = out + (size_t)BATCH * 3 * NPTS + ((size_t)b * 64) * NPTS + n0;
#pragma unroll
    for (int jj = 0; jj < 4; jj++) {
        const int d = 4 * to + jj;
        float4 r = *(const float4*)(pin + (size_t)d * NPTS);
        float4 y;
        y.x = fmaxf(0.f, fmaf(A2[d], acc[0][jj], C2[d]) + r.x);
        y.y = fmaxf(0.f, fmaf(A2[d], acc[1][jj], C2[d]) + r.y);
        y.z = fmaxf(0.f, fmaf(A2[d], acc[2][jj], C2[d]) + r.z);
        y.w = fmaxf(0.f, fmaf(A2[d], acc[3][jj], C2[d]) + r.w);
        *(float4*)(pout + (size_t)d * NPTS) = y;
    }
}

// ============================================================================
extern "C" void kernel_launch(void* const* d_in, const int* in_sizes, int n_in,
                              void* d_out, int out_size) {
    const float* xyz    = (const float*)d_in[0];
    const float* points = (const float*)d_in[1];
    const float* W      = (const float*)d_in[2];
    const float* bconv  = (const float*)d_in[3];
    const float* g      = (const float*)d_in[4];
    const float* bt     = (const float*)d_in[5];
    const float* rm     = (const float*)d_in[6];
    const float* rv     = (const float*)d_in[7];
    const float* W1     = (const float*)d_in[8];
    const float* b1     = (const float*)d_in[9];
    const float* g1     = (const float*)d_in[10];
    const float* bt1    = (const float*)d_in[11];
    const float* rm1    = (const float*)d_in[12];
    const float* rv1    = (const float*)d_in[13];
    const float* W2     = (const float*)d_in[14];
    const float* b2     = (const float*)d_in[15];
    const float* g2     = (const float*)d_in[16];
    const float* bt2    = (const float*)d_in[17];
    const float* rm2    = (const float*)d_in[18];
    const float* rv2    = (const float*)d_in[19];
    float* out = (float*)d_out;

    cudaMemcpyAsync(out, xyz, (size_t)BATCH * 3 * NPTS * sizeof(float),
                    cudaMemcpyDeviceToDevice, 0);

    k1_fg<<<(BATCH * NPTS) / 64, 256>>>(xyz, points, W);
    k2_ball<<<(BATCH * NPTS) / 2, 64>>>(W, bconv, g, bt, rm, rv);

    const int k3a_smem = (64 * XP + 64 * WP1 + 2 * PH) * (int)sizeof(float);
    cudaFuncSetAttribute(k3a, cudaFuncAttributeMaxDynamicSharedMemorySize, k3a_smem);
    k3a<<<(BATCH * NPTS) / 64, 256, k3a_smem>>>(W1, b1, g1, bt1, rm1, rv1);

    const int k3b_smem = (PH * HP + PH * WP2 + 2 * 64) * (int)sizeof(float);
    cudaFuncSetAttribute(k3b, cudaFuncAttributeMaxDynamicSharedMemorySize, k3b_smem);
    k3b<<<(BATCH * NPTS) / 64, 256, k3b_smem>>>(W2, b2, g2, bt2, rm2, rv2, points, out);

    (void)in_sizes; (void)n_in; (void)out_size;
}

// round 5
// speedup vs baseline: 1.0915x; 1.0281x over previous
#include <cuda_runtime.h>

#define BATCH 8
#define NPTS  4096
#define KNN   32
#define DIM   64
#define CIN   67
#define PH    128
#define EPSF  1e-5f

// ---------------- static device scratch (no allocs allowed) ----------------
__device__ __align__(256) float  d_FG[BATCH * NPTS * DIM];    // 8 MB
__device__ __align__(256) float4 d_xyzw[BATCH * NPTS];        // 512 KB
__device__ __align__(256) float  d_newp[BATCH * NPTS * DIM];  // 8 MB  [pt][c]

// ============================================================================
// k1: FG[pt][o] = sum_{c<64} points[b,c,n]*W[o,c] + sum_{j<3} xyz[b,j,n]*W[o,64+j]
// 256 threads = 64 points x 4 output-quarters (16 outputs per thread).
// ============================================================================
__global__ __launch_bounds__(256) void k1_fg(const float* __restrict__ xyz,
                                             const float* __restrict__ points,
                                             const float* __restrict__ W) {
    __shared__ float Wsh[64][68];
    const int tid = threadIdx.x;
    const int p   = tid & 63;
    const int g   = tid >> 6;

    for (int i = tid; i < 64 * CIN; i += 256) Wsh[i / CIN][i % CIN] = W[i];
    __syncthreads();

    const int pt = blockIdx.x * 64 + p;
    const int b  = pt >> 12;
    const int n  = pt & (NPTS - 1);

    float in[CIN];
    {
        const float* pb = points + ((size_t)b * DIM) * NPTS + n;
#pragma unroll
        for (int c = 0; c < 64; c++) in[c] = pb[(size_t)c * NPTS];
        const float* xb = xyz + ((size_t)b * 3) * NPTS + n;
        float x = xb[0], y = xb[NPTS], z = xb[2 * NPTS];
        in[64] = x; in[65] = y; in[66] = z;
        if (g == 0) {
            float sq = __fadd_rn(__fadd_rn(__fmul_rn(x, x), __fmul_rn(y, y)), __fmul_rn(z, z));
            d_xyzw[pt] = make_float4(x, y, z, sq);
        }
    }

    const int o0 = 16 * g;
    float out16[16];
#pragma unroll
    for (int oo = 0; oo < 16; oo++) {
        const int o = o0 + oo;
        const float4* wrow = (const float4*)&Wsh[o][0];
        float acc = 0.f;
#pragma unroll
        for (int q = 0; q < 16; q++) {
            float4 w4 = wrow[q];
            acc = fmaf(in[4 * q + 0], w4.x, acc);
            acc = fmaf(in[4 * q + 1], w4.y, acc);
            acc = fmaf(in[4 * q + 2], w4.z, acc);
            acc = fmaf(in[4 * q + 3], w4.w, acc);
        }
        acc = fmaf(in[64], Wsh[o][64], acc);
        acc = fmaf(in[65], Wsh[o][65], acc);
        acc = fmaf(in[66], Wsh[o][66], acc);
        out16[oo] = acc;
    }
    float* dst = d_FG + (size_t)pt * 64 + o0;
#pragma unroll
    for (int s = 0; s < 4; s++)
        *(float4*)(dst + 4 * s) = make_float4(out16[4 * s], out16[4 * s + 1],
                                              out16[4 * s + 2], out16[4 * s + 3]);
}

// ============================================================================
// k2: 8 warps/block (8 queries, same batch). Candidate tiles of 512 points
// staged in smem by the whole block; each warp scans from smem with
// ascending-index semantics + early exit at 32 hits; block exits when all
// warps are done. Then fixed 16x LDG.128 FG-row gather + BN/ReLU epilogue.
// ============================================================================
#define K2TILE 512
__global__ __launch_bounds__(256) void k2_ball(const float* __restrict__ W,
                                               const float* __restrict__ bconv,
                                               const float* __restrict__ g,
                                               const float* __restrict__ bt,
                                               const float* __restrict__ rm,
                                               const float* __restrict__ rv) {
    __shared__ float4 tile[K2TILE];     // 8 KB
    __shared__ int idxbuf[8][KNN];      // 1 KB
    const int tid  = threadIdx.x;
    const int lane = tid & 31;
    const int w    = tid >> 5;
    const int gw   = blockIdx.x * 8 + w;
    const int b    = gw >> 12;

    const float4 q = d_xyzw[gw];
    int* buf = idxbuf[w];
    int count = 0;
    const float4* xb = d_xyzw + ((size_t)b << 12);
    const unsigned ltmask = (1u << lane) - 1u;

    for (int base = 0; base < NPTS; base += K2TILE) {
        // stage 512 candidates (all threads; prior tile readers are past the
        // __syncthreads_and barrier from the previous iteration)
        tile[tid]       = xb[base + tid];
        tile[tid + 256] = xb[base + tid + 256];
        __syncthreads();

        if (count < KNN) {
#pragma unroll 2
            for (int s = 0; s < K2TILE; s += 32) {
                float4 p = tile[s + lane];
                float dot  = fmaf(q.z, p.z, fmaf(q.y, p.y, __fmul_rn(q.x, p.x)));
                float dist = __fsub_rn(__fadd_rn(q.w, p.w), __fmul_rn(2.0f, dot));
                unsigned m = __ballot_sync(0xffffffffu, !(dist > 0.04f));
                int pos = count + __popc(m & ltmask);
                if ((m >> lane) & 1u) { if (pos < KNN) buf[pos] = base + s + lane; }
                count += __popc(m);
                if (count >= KNN) break;
            }
        }
        if (__syncthreads_and(count >= KNN)) break;
    }

    int cnt = min(count, KNN);
    if (lane >= cnt) buf[lane] = buf[0];   // pad == reference pad-with-first
    __syncwarp();

    // gather: half-warp h handles rows 2k+h; lane j owns channels 4j..4j+3
    const int h = lane >> 4, j = lane & 15;
    const float* rowbase = d_FG + (((size_t)b << 12) * 64) + 4 * j;
    float mx[4] = {-3.4e38f, -3.4e38f, -3.4e38f, -3.4e38f};
    float mn[4] = { 3.4e38f,  3.4e38f,  3.4e38f,  3.4e38f};
#pragma unroll
    for (int k = 0; k < 16; k++) {
        int i = buf[2 * k + h];
        float4 v = *(const float4*)(rowbase + (size_t)i * 64);
        mx[0] = fmaxf(mx[0], v.x); mn[0] = fminf(mn[0], v.x);
        mx[1] = fmaxf(mx[1], v.y); mn[1] = fminf(mn[1], v.y);
        mx[2] = fmaxf(mx[2], v.z); mn[2] = fminf(mn[2], v.z);
        mx[3] = fmaxf(mx[3], v.w); mn[3] = fminf(mn[3], v.w);
    }
#pragma unroll
    for (int u = 0; u < 4; u++) {
        mx[u] = fmaxf(mx[u], __shfl_xor_sync(0xffffffffu, mx[u], 16));
        mn[u] = fminf(mn[u], __shfl_xor_sync(0xffffffffu, mn[u], 16));
    }

    if (h == 0) {
        const int c = 4 * j;
        float y[4];
#pragma unroll
        for (int u = 0; u < 4; u++) {
            const int cu = c + u;
            float G = fmaf(q.z, W[cu * CIN + 66],
                      fmaf(q.y, W[cu * CIN + 65], __fmul_rn(q.x, W[cu * CIN + 64])));
            float s = g[cu] * rsqrtf(rv[cu] + EPSF);
            float C = fmaf(s, bconv[cu] - rm[cu], bt[cu]);
            float E = (s >= 0.f) ? mx[u] : mn[u];
            y[u] = fmaxf(0.f, fmaf(s, E - G, C));
        }
        *(float4*)(d_newp + (size_t)gw * 64 + c) = make_float4(y[0], y[1], y[2], y[3]);
    }
}

// ============================================================================
// k3: fully fused resnet. Block = 64 points, 256 threads.
//   Phase A: GEMM1 64c -> 128o (4x8 tiles), BN+ReLU, H kept in smem (p-major).
//   Phase B: GEMM2 128o -> 64d (4x4 tiles, o-step 4), BN + residual + ReLU.
// W2^T is staged into the reclaimed X/W1 smem region — no DRAM round trip.
// ============================================================================
#define XP   68
#define W1P  132
#define HPD  132
#define W2P  68
#define OFF_XS   0
#define OFF_W1   (64 * XP)                 // 4352
#define OFF_HS   (OFF_W1 + 64 * W1P)       // 12800
#define OFF_CST  (OFF_HS + 64 * HPD)       // 21248
#define K3_SMEMF (OFF_CST + 384)           // 21632 floats = 86528 B

__global__ __launch_bounds__(256) void k3_fused(
        const float* __restrict__ W1, const float* __restrict__ b1,
        const float* __restrict__ g1, const float* __restrict__ bt1,
        const float* __restrict__ rm1, const float* __restrict__ rv1,
        const float* __restrict__ W2, const float* __restrict__ b2,
        const float* __restrict__ g2, const float* __restrict__ bt2,
        const float* __restrict__ rm2, const float* __restrict__ rv2,
        const float* __restrict__ points, float* __restrict__ out) {
    extern __shared__ float sm[];
    float* Xs   = sm + OFF_XS;     // [64 c][XP]
    float* W1Ts = sm + OFF_W1;     // [64 c][W1P]
    float* Hs   = sm + OFF_HS;     // [64 p][HPD]   (p-major)
    float* W2Ts = sm + OFF_XS;     // [128 o][W2P]  (reuses Xs+W1Ts after phase A)
    float* A1   = sm + OFF_CST;         // 128
    float* C1   = A1 + 128;             // 128
    float* A2   = C1 + 128;             // 64
    float* C2   = A2 + 64;              // 64

    const int tid  = threadIdx.x;
    const int base = blockIdx.x * 64;

    for (int t = tid; t < 64 * 16; t += 256) {          // np tile, transposed
        int p = t >> 4, qc = t & 15;
        float4 v = *(const float4*)(d_newp + (size_t)(base + p) * 64 + 4 * qc);
        Xs[(4 * qc + 0) * XP + p] = v.x;
        Xs[(4 * qc + 1) * XP + p] = v.y;
        Xs[(4 * qc + 2) * XP + p] = v.z;
        Xs[(4 * qc + 3) * XP + p] = v.w;
    }
    for (int t = tid; t < PH * 64; t += 256) {          // W1 [o][c] -> [c][o]
        int o = t >> 6, c = t & 63;
        W1Ts[c * W1P + o] = W1[t];
    }
    if (tid < PH) {
        float s = g1[tid] * rsqrtf(rv1[tid] + EPSF);
        A1[tid] = s;
        C1[tid] = fmaf(s, b1[tid] - rm1[tid], bt1[tid]);
    }
    if (tid >= 128 && tid < 192) {
        int d = tid - 128;
        float s = g2[d] * rsqrtf(rv2[d] + EPSF);
        A2[d] = s;
        C2[d] = fmaf(s, b2[d] - rm2[d], bt2[d]);
    }
    __syncthreads();

    // ---- Phase A: GEMM1 (4 points x 8 outputs per thread) ----
    const int to = tid & 15;       // o-group: 8*to
    const int tp = tid >> 4;       // p-group: 4*tp
    float acc[4][8];
#pragma unroll
    for (int i = 0; i < 4; i++)
#pragma unroll
        for (int jj = 0; jj < 8; jj++) acc[i][jj] = 0.f;

#pragma unroll 8
    for (int c = 0; c < 64; c++) {
        float4 x  = *(const float4*)&Xs[c * XP + 4 * tp];
        float4 wa = *(const float4*)&W1Ts[c * W1P + 8 * to];
        float4 wb = *(const float4*)&W1Ts[c * W1P + 8 * to + 4];
        float xv[4] = {x.x, x.y, x.z, x.w};
        float wv[8] = {wa.x, wa.y, wa.z, wa.w, wb.x, wb.y, wb.z, wb.w};
#pragma unroll
        for (int i = 0; i < 4; i++)
#pragma unroll
            for (int jj = 0; jj < 8; jj++)
                acc[i][jj] = fmaf(xv[i], wv[jj], acc[i][jj]);
    }

#pragma unroll
    for (int i = 0; i < 4; i++) {
        const int p = 4 * tp + i;
        float hv[8];
#pragma unroll
        for (int jj = 0; jj < 8; jj++) {
            int o = 8 * to + jj;
            hv[jj] = fmaxf(0.f, fmaf(A1[o], acc[i][jj], C1[o]));
        }
        *(float4*)&Hs[p * HPD + 8 * to]     = make_float4(hv[0], hv[1], hv[2], hv[3]);
        *(float4*)&Hs[p * HPD + 8 * to + 4] = make_float4(hv[4], hv[5], hv[6], hv[7]);
    }
    __syncthreads();

    // ---- stage W2^T into reclaimed region ----
    for (int t = tid; t < 64 * PH; t += 256) {          // W2 [d][o] -> [o][d]
        int d = t >> 7, o = t & 127;
        W2Ts[o * W2P + d] = W2[t];
    }
    __syncthreads();

    // ---- Phase B: GEMM2 (4 points x 4 outputs, o-step 4) ----
    float acc2[4][4];
#pragma unroll
    for (int i = 0; i < 4; i++)
#pragma unroll
        for (int jj = 0; jj < 4; jj++) acc2[i][jj] = 0.f;

#pragma unroll 4
    for (int o = 0; o < PH; o += 4) {
        float4 h0 = *(const float4*)&Hs[(4 * tp + 0) * HPD + o];
        float4 h1 = *(const float4*)&Hs[(4 * tp + 1) * HPD + o];
        float4 h2 = *(const float4*)&Hs[(4 * tp + 2) * HPD + o];
        float4 h3 = *(const float4*)&Hs[(4 * tp + 3) * HPD + o];
        float4 w0 = *(const float4*)&W2Ts[(o + 0) * W2P + 4 * to];
        float4 w1 = *(const float4*)&W2Ts[(o + 1) * W2P + 4 * to];
        float4 w2 = *(const float4*)&W2Ts[(o + 2) * W2P + 4 * to];
        float4 w3 = *(const float4*)&W2Ts[(o + 3) * W2P + 4 * to];
        float hvs[4][4] = {{h0.x, h0.y, h0.z, h0.w}, {h1.x, h1.y, h1.z, h1.w},
                           {h2.x, h2.y, h2.z, h2.w}, {h3.x, h3.y, h3.z, h3.w}};
        float wvs[4][4] = {{w0.x, w0.y, w0.z, w0.w}, {w1.x, w1.y, w1.z, w1.w},
                           {w2.x, w2.y, w2.z, w2.w}, {w3.x, w3.y, w3.z, w3.w}};
#pragma unroll
        for (int i = 0; i < 4; i++)
#pragma unroll
            for (int k = 0; k < 4; k++)
#pragma unroll
                for (int jj = 0; jj < 4; jj++)
                    acc2[i][jj] = fmaf(hvs[i][k], wvs[k][jj], acc2[i][jj]);
    }

    const int b  = base >> 12;
    const int n0 = (base & (NPTS - 1)) + 4 * tp;
    const float* pin = points + ((size_t)b * 64) * NPTS + n0;
    float* pout = out + (size_t)BATCH * 3 * NPTS + ((size_t)b * 64) * NPTS + n0;
#pragma unroll
    for (int jj = 0; jj < 4; jj++) {
        const int d = 4 * to + jj;
        float4 r = *(const float4*)(pin + (size_t)d * NPTS);
        float4 y;
        y.x = fmaxf(0.f, fmaf(A2[d], acc2[0][jj], C2[d]) + r.x);
        y.y = fmaxf(0.f, fmaf(A2[d], acc2[1][jj], C2[d]) + r.y);
        y.z = fmaxf(0.f, fmaf(A2[d], acc2[2][jj], C2[d]) + r.z);
        y.w = fmaxf(0.f, fmaf(A2[d], acc2[3][jj], C2[d]) + r.w);
        *(float4*)(pout + (size_t)d * NPTS) = y;
    }
}

// ============================================================================
extern "C" void kernel_launch(void* const* d_in, const int* in_sizes, int n_in,
                              void* d_out, int out_size) {
    const float* xyz    = (const float*)d_in[0];
    const float* points = (const float*)d_in[1];
    const float* W      = (const float*)d_in[2];
    const float* bconv  = (const float*)d_in[3];
    const float* g      = (const float*)d_in[4];
    const float* bt     = (const float*)d_in[5];
    const float* rm     = (const float*)d_in[6];
    const float* rv     = (const float*)d_in[7];
    const float* W1     = (const float*)d_in[8];
    const float* b1     = (const float*)d_in[9];
    const float* g1     = (const float*)d_in[10];
    const float* bt1    = (const float*)d_in[11];
    const float* rm1    = (const float*)d_in[12];
    const float* rv1    = (const float*)d_in[13];
    const float* W2     = (const float*)d_in[14];
    const float* b2     = (const float*)d_in[15];
    const float* g2     = (const float*)d_in[16];
    const float* bt2    = (const float*)d_in[17];
    const float* rm2    = (const float*)d_in[18];
    const float* rv2    = (const float*)d_in[19];
    float* out = (float*)d_out;

    cudaMemcpyAsync(out, xyz, (size_t)BATCH * 3 * NPTS * sizeof(float),
                    cudaMemcpyDeviceToDevice, 0);

    k1_fg<<<(BATCH * NPTS) / 64, 256>>>(xyz, points, W);
    k2_ball<<<(BATCH * NPTS) / 8, 256>>>(W, bconv, g, bt, rm, rv);

    const int k3_smem = K3_SMEMF * (int)sizeof(float);
    cudaFuncSetAttribute(k3_fused, cudaFuncAttributeMaxDynamicSharedMemorySize, k3_smem);
    k3_fused<<<(BATCH * NPTS) / 64, 256, k3_smem>>>(W1, b1, g1, bt1, rm1, rv1,
                                                    W2, b2, g2, bt2, rm2, rv2,
                                                    points, out);
    (void)in_sizes; (void)n_in; (void)out_size;
}

// round 7
// speedup vs baseline: 1.1868x; 1.0873x over previous
#include <cuda_runtime.h>

#define BATCH 8
#define NPTS  4096
#define KNN   32
#define DIM   64
#define CIN   67
#define PH    128
#define EPSF  1e-5f

// ---------------- static device scratch (no allocs allowed) ----------------
__device__ __align__(256) float  d_FG[BATCH * NPTS * DIM];    // 8 MB
__device__ __align__(256) float4 d_xyzw[BATCH * NPTS];        // 512 KB
__device__ __align__(256) float  d_newp[BATCH * NPTS * DIM];  // 8 MB  [pt][c]

// ============================================================================
// k1: FG[pt][o] = sum_{c<64} points[b,c,n]*W[o,c] + sum_{j<3} xyz[b,j,n]*W[o,64+j]
// 256 threads = 64 points x 4 output-quarters (16 outputs per thread).
// Inputs streamed in 4 chunks of 16 regs -> no spills (same c-ascending order).
// ============================================================================
__global__ __launch_bounds__(256) void k1_fg(const float* __restrict__ xyz,
                                             const float* __restrict__ points,
                                             const float* __restrict__ W) {
    __shared__ float Wsh[64][68];
    const int tid = threadIdx.x;
    const int p   = tid & 63;
    const int g   = tid >> 6;

    for (int i = tid; i < 64 * CIN; i += 256) Wsh[i / CIN][i % CIN] = W[i];
    __syncthreads();

    const int pt = blockIdx.x * 64 + p;
    const int b  = pt >> 12;
    const int n  = pt & (NPTS - 1);
    const int o0 = 16 * g;
    const float* pb = points + ((size_t)b * DIM) * NPTS + n;

    float acc16[16];
#pragma unroll
    for (int oo = 0; oo < 16; oo++) acc16[oo] = 0.f;

#pragma unroll
    for (int cc = 0; cc < 4; cc++) {
        float in16[16];
#pragma unroll
        for (int j = 0; j < 16; j++)
            in16[j] = pb[(size_t)(16 * cc + j) * NPTS];
#pragma unroll
        for (int oo = 0; oo < 16; oo++) {
            const float4* wrow = (const float4*)&Wsh[o0 + oo][16 * cc];
            float a = acc16[oo];
#pragma unroll
            for (int q = 0; q < 4; q++) {
                float4 w4 = wrow[q];
                a = fmaf(in16[4 * q + 0], w4.x, a);
                a = fmaf(in16[4 * q + 1], w4.y, a);
                a = fmaf(in16[4 * q + 2], w4.z, a);
                a = fmaf(in16[4 * q + 3], w4.w, a);
            }
            acc16[oo] = a;
        }
    }

    // xyz tail (c = 64..66) + xyzw pack
    {
        const float* xb = xyz + ((size_t)b * 3) * NPTS + n;
        float x = xb[0], y = xb[NPTS], z = xb[2 * NPTS];
#pragma unroll
        for (int oo = 0; oo < 16; oo++) {
            const int o = o0 + oo;
            float a = acc16[oo];
            a = fmaf(x, Wsh[o][64], a);
            a = fmaf(y, Wsh[o][65], a);
            a = fmaf(z, Wsh[o][66], a);
            acc16[oo] = a;
        }
        if (g == 0) {
            float sq = __fadd_rn(__fadd_rn(__fmul_rn(x, x), __fmul_rn(y, y)), __fmul_rn(z, z));
            d_xyzw[pt] = make_float4(x, y, z, sq);
        }
    }

    float* dst = d_FG + (size_t)pt * 64 + o0;
#pragma unroll
    for (int s = 0; s < 4; s++)
        *(float4*)(dst + 4 * s) = make_float4(acc16[4 * s], acc16[4 * s + 1],
                                              acc16[4 * s + 2], acc16[4 * s + 3]);
}

// ============================================================================
// k2: warp per query (warp-autonomous early exit). Scan 64 points/iter.
// Pad index list to 32 with buf[0] (== reference pad-with-first).
// Fixed 16x LDG.128 FG-row gather + BN/ReLU epilogue.
// ============================================================================
__global__ __launch_bounds__(64) void k2_ball(const float* __restrict__ W,
                                              const float* __restrict__ bconv,
                                              const float* __restrict__ g,
                                              const float* __restrict__ bt,
                                              const float* __restrict__ rm,
                                              const float* __restrict__ rv) {
    __shared__ int idxbuf[2][KNN];
    const int lane = threadIdx.x & 31;
    const int w    = threadIdx.x >> 5;
    const int gw   = blockIdx.x * 2 + w;
    const int b    = gw >> 12;

    const float4 q = d_xyzw[gw];
    int* buf = idxbuf[w];
    int count = 0;
    const float4* xb = d_xyzw + ((size_t)b << 12);
    const unsigned ltmask = (1u << lane) - 1u;

    for (int base = 0; base < NPTS; base += 64) {
        float4 p0 = xb[base + lane];
        float4 p1 = xb[base + 32 + lane];
        float dot0 = fmaf(q.z, p0.z, fmaf(q.y, p0.y, __fmul_rn(q.x, p0.x)));
        float d0   = __fsub_rn(__fadd_rn(q.w, p0.w), __fmul_rn(2.0f, dot0));
        float dot1 = fmaf(q.z, p1.z, fmaf(q.y, p1.y, __fmul_rn(q.x, p1.x)));
        float d1   = __fsub_rn(__fadd_rn(q.w, p1.w), __fmul_rn(2.0f, dot1));
        unsigned m0 = __ballot_sync(0xffffffffu, !(d0 > 0.04f));
        unsigned m1 = __ballot_sync(0xffffffffu, !(d1 > 0.04f));
        int c0 = __popc(m0);
        int pos0 = count + __popc(m0 & ltmask);
        if ((m0 >> lane) & 1u) { if (pos0 < KNN) buf[pos0] = base + lane; }
        int pos1 = count + c0 + __popc(m1 & ltmask);
        if ((m1 >> lane) & 1u) { if (pos1 < KNN) buf[pos1] = base + 32 + lane; }
        count += c0 + __popc(m1);
        if (count >= KNN) break;
    }
    __syncwarp();
    int cnt = min(count, KNN);
    if (lane >= cnt) buf[lane] = buf[0];
    __syncwarp();

    // gather: half-warp h handles rows 2k+h; lane j owns channels 4j..4j+3
    const int h = lane >> 4, j = lane & 15;
    const float* rowbase = d_FG + (((size_t)b << 12) * 64) + 4 * j;
    float mx[4] = {-3.4e38f, -3.4e38f, -3.4e38f, -3.4e38f};
    float mn[4] = { 3.4e38f,  3.4e38f,  3.4e38f,  3.4e38f};
#pragma unroll
    for (int k = 0; k < 16; k++) {
        int i = buf[2 * k + h];
        float4 v = *(const float4*)(rowbase + (size_t)i * 64);
        mx[0] = fmaxf(mx[0], v.x); mn[0] = fminf(mn[0], v.x);
        mx[1] = fmaxf(mx[1], v.y); mn[1] = fminf(mn[1], v.y);
        mx[2] = fmaxf(mx[2], v.z); mn[2] = fminf(mn[2], v.z);
        mx[3] = fmaxf(mx[3], v.w); mn[3] = fminf(mn[3], v.w);
    }
#pragma unroll
    for (int u = 0; u < 4; u++) {
        mx[u] = fmaxf(mx[u], __shfl_xor_sync(0xffffffffu, mx[u], 16));
        mn[u] = fminf(mn[u], __shfl_xor_sync(0xffffffffu, mn[u], 16));
    }

    if (h == 0) {
        const int c = 4 * j;
        float y[4];
#pragma unroll
        for (int u = 0; u < 4; u++) {
            const int cu = c + u;
            float G = fmaf(q.z, __ldg(&W[cu * CIN + 66]),
                      fmaf(q.y, __ldg(&W[cu * CIN + 65]),
                           __fmul_rn(q.x, __ldg(&W[cu * CIN + 64]))));
            float s = __ldg(&g[cu]) * rsqrtf(__ldg(&rv[cu]) + EPSF);
            float C = fmaf(s, __ldg(&bconv[cu]) - __ldg(&rm[cu]), __ldg(&bt[cu]));
            float E = (s >= 0.f) ? mx[u] : mn[u];
            y[u] = fmaxf(0.f, fmaf(s, E - G, C));
        }
        *(float4*)(d_newp + (size_t)gw * 64 + c) = make_float4(y[0], y[1], y[2], y[3]);
    }
}

// ============================================================================
// k3: fully fused resnet. Block = 64 points, 256 threads.
//   Phase A: GEMM1 64c -> 128o (4x8 tiles), BN+ReLU, H kept in smem (p-major).
//   Phase B: GEMM2 128o -> 64d (4x4 tiles, o-step 4), BN + residual + ReLU.
// W2^T is staged into the reclaimed X/W1 smem region — no DRAM round trip.
// ============================================================================
#define XP   68
#define W1P  132
#define HPD  132
#define W2P  68
#define OFF_XS   0
#define OFF_W1   (64 * XP)
#define OFF_HS   (OFF_W1 + 64 * W1P)
#define OFF_CST  (OFF_HS + 64 * HPD)
#define K3_SMEMF (OFF_CST + 384)

__global__ __launch_bounds__(256) void k3_fused(
        const float* __restrict__ W1, const float* __restrict__ b1,
        const float* __restrict__ g1, const float* __restrict__ bt1,
        const float* __restrict__ rm1, const float* __restrict__ rv1,
        const float* __restrict__ W2, const float* __restrict__ b2,
        const float* __restrict__ g2, const float* __restrict__ bt2,
        const float* __restrict__ rm2, const float* __restrict__ rv2,
        const float* __restrict__ points, float* __restrict__ out) {
    extern __shared__ float sm[];
    float* Xs   = sm + OFF_XS;     // [64 c][XP]
    float* W1Ts = sm + OFF_W1;     // [64 c][W1P]
    float* Hs   = sm + OFF_HS;     // [64 p][HPD]
    float* W2Ts = sm + OFF_XS;     // [128 o][W2P]  (reuses Xs+W1Ts)
    float* A1   = sm + OFF_CST;
    float* C1   = A1 + 128;
    float* A2   = C1 + 128;
    float* C2   = A2 + 64;

    const int tid  = threadIdx.x;
    const int base = blockIdx.x * 64;

    for (int t = tid; t < 64 * 16; t += 256) {
        int p = t >> 4, qc = t & 15;
        float4 v = *(const float4*)(d_newp + (size_t)(base + p) * 64 + 4 * qc);
        Xs[(4 * qc + 0) * XP + p] = v.x;
        Xs[(4 * qc + 1) * XP + p] = v.y;
        Xs[(4 * qc + 2) * XP + p] = v.z;
        Xs[(4 * qc + 3) * XP + p] = v.w;
    }
    for (int t = tid; t < PH * 64; t += 256) {
        int o = t >> 6, c = t & 63;
        W1Ts[c * W1P + o] = W1[t];
    }
    if (tid < PH) {
        float s = g1[tid] * rsqrtf(rv1[tid] + EPSF);
        A1[tid] = s;
        C1[tid] = fmaf(s, b1[tid] - rm1[tid], bt1[tid]);
    }
    if (tid >= 128 && tid < 192) {
        int d = tid - 128;
        float s = g2[d] * rsqrtf(rv2[d] + EPSF);
        A2[d] = s;
        C2[d] = fmaf(s, b2[d] - rm2[d], bt2[d]);
    }
    __syncthreads();

    const int to = tid & 15;
    const int tp = tid >> 4;
    float acc[4][8];
#pragma unroll
    for (int i = 0; i < 4; i++)
#pragma unroll
        for (int jj = 0; jj < 8; jj++) acc[i][jj] = 0.f;

#pragma unroll 8
    for (int c = 0; c < 64; c++) {
        float4 x  = *(const float4*)&Xs[c * XP + 4 * tp];
        float4 wa = *(const float4*)&W1Ts[c * W1P + 8 * to];
        float4 wb = *(const float4*)&W1Ts[c * W1P + 8 * to + 4];
        float xv[4] = {x.x, x.y, x.z, x.w};
        float wv[8] = {wa.x, wa.y, wa.z, wa.w, wb.x, wb.y, wb.z, wb.w};
#pragma unroll
        for (int i = 0; i < 4; i++)
#pragma unroll
            for (int jj = 0; jj < 8; jj++)
                acc[i][jj] = fmaf(xv[i], wv[jj], acc[i][jj]);
    }

#pragma unroll
    for (int i = 0; i < 4; i++) {
        const int p = 4 * tp + i;
        float hv[8];
#pragma unroll
        for (int jj = 0; jj < 8; jj++) {
            int o = 8 * to + jj;
            hv[jj] = fmaxf(0.f, fmaf(A1[o], acc[i][jj], C1[o]));
        }
        *(float4*)&Hs[p * HPD + 8 * to]     = make_float4(hv[0], hv[1], hv[2], hv[3]);
        *(float4*)&Hs[p * HPD + 8 * to + 4] = make_float4(hv[4], hv[5], hv[6], hv[7]);
    }
    __syncthreads();

    for (int t = tid; t < 64 * PH; t += 256) {
        int d = t >> 7, o = t & 127;
        W2Ts[o * W2P + d] = W2[t];
    }
    __syncthreads();

    float acc2[4][4];
#pragma unroll
    for (int i = 0; i < 4; i++)
#pragma unroll
        for (int jj = 0; jj < 4; jj++) acc2[i][jj] = 0.f;

#pragma unroll 4
    for (int o = 0; o < PH; o += 4) {
        float4 h0 = *(const float4*)&Hs[(4 * tp + 0) * HPD + o];
        float4 h1 = *(const float4*)&Hs[(4 * tp + 1) * HPD + o];
        float4 h2 = *(const float4*)&Hs[(4 * tp + 2) * HPD + o];
        float4 h3 = *(const float4*)&Hs[(4 * tp + 3) * HPD + o];
        float4 w0 = *(const float4*)&W2Ts[(o + 0) * W2P + 4 * to];
        float4 w1 = *(const float4*)&W2Ts[(o + 1) * W2P + 4 * to];
        float4 w2 = *(const float4*)&W2Ts[(o + 2) * W2P + 4 * to];
        float4 w3 = *(const float4*)&W2Ts[(o + 3) * W2P + 4 * to];
        float hvs[4][4] = {{h0.x, h0.y, h0.z, h0.w}, {h1.x, h1.y, h1.z, h1.w},
                           {h2.x, h2.y, h2.z, h2.w}, {h3.x, h3.y, h3.z, h3.w}};
        float wvs[4][4] = {{w0.x, w0.y, w0.z, w0.w}, {w1.x, w1.y, w1.z, w1.w},
                           {w2.x, w2.y, w2.z, w2.w}, {w3.x, w3.y, w3.z, w3.w}};
#pragma unroll
        for (int i = 0; i < 4; i++)
#pragma unroll
            for (int k = 0; k < 4; k++)
#pragma unroll
                for (int jj = 0; jj < 4; jj++)
                    acc2[i][jj] = fmaf(hvs[i][k], wvs[k][jj], acc2[i][jj]);
    }

    const int b  = base >> 12;
    const int n0 = (base & (NPTS - 1)) + 4 * tp;
    const float* pin = points + ((size_t)b * 64) * NPTS + n0;
    float* pout = out + (size_t)BATCH * 3 * NPTS + ((size_t)b * 64) * NPTS + n0;
#pragma unroll
    for (int jj = 0; jj < 4; jj++) {
        const int d = 4 * to + jj;
        float4 r = *(const float4*)(pin + (size_t)d * NPTS);
        float4 y;
        y.x = fmaxf(0.f, fmaf(A2[d], acc2[0][jj], C2[d]) + r.x);
        y.y = fmaxf(0.f, fmaf(A2[d], acc2[1][jj], C2[d]) + r.y);
        y.z = fmaxf(0.f, fmaf(A2[d], acc2[2][jj], C2[d]) + r.z);
        y.w = fmaxf(0.f, fmaf(A2[d], acc2[3][jj], C2[d]) + r.w);
        *(float4*)(pout + (size_t)d * NPTS) = y;
    }
}

// ============================================================================
extern "C" void kernel_launch(void* const* d_in, const int* in_sizes, int n_in,
                              void* d_out, int out_size) {
    const float* xyz    = (const float*)d_in[0];
    const float* points = (const float*)d_in[1];
    const float* W      = (const float*)d_in[2];
    const float* bconv  = (const float*)d_in[3];
    const float* g      = (const float*)d_in[4];
    const float* bt     = (const float*)d_in[5];
    const float* rm     = (const float*)d_in[6];
    const float* rv     = (const float*)d_in[7];
    const float* W1     = (const float*)d_in[8];
    const float* b1     = (const float*)d_in[9];
    const float* g1     = (const float*)d_in[10];
    const float* bt1    = (const float*)d_in[11];
    const float* rm1    = (const float*)d_in[12];
    const float* rv1    = (const float*)d_in[13];
    const float* W2     = (const float*)d_in[14];
    const float* b2     = (const float*)d_in[15];
    const float* g2     = (const float*)d_in[16];
    const float* bt2    = (const float*)d_in[17];
    const float* rm2    = (const float*)d_in[18];
    const float* rv2    = (const float*)d_in[19];
    float* out = (float*)d_out;

    cudaMemcpyAsync(out, xyz, (size_t)BATCH * 3 * NPTS * sizeof(float),
                    cudaMemcpyDeviceToDevice, 0);

    k1_fg<<<(BATCH * NPTS) / 64, 256>>>(xyz, points, W);
    k2_ball<<<(BATCH * NPTS) / 2, 64>>>(W, bconv, g, bt, rm, rv);

    const int k3_smem = K3_SMEMF * (int)sizeof(float);
    cudaFuncSetAttribute(k3_fused, cudaFuncAttributeMaxDynamicSharedMemorySize, k3_smem);
    k3_fused<<<(BATCH * NPTS) / 64, 256, k3_smem>>>(W1, b1, g1, bt1, rm1, rv1,
                                                    W2, b2, g2, bt2, rm2, rv2,
                                                    points, out);
    (void)in_sizes; (void)n_in; (void)out_size;
}

// round 9
// speedup vs baseline: 1.2657x; 1.0665x over previous
#include <cuda_runtime.h>

#define BATCH 8
#define NPTS  4096
#define KNN   32
#define DIM   64
#define CIN   67
#define PH    128
#define EPSF  1e-5f

// ---------------- static device scratch (no allocs allowed) ----------------
__device__ __align__(256) float  d_FG[BATCH * NPTS * DIM];    // 8 MB
__device__ __align__(256) float4 d_xyzw[BATCH * NPTS];        // 512 KB
__device__ __align__(256) float  d_newp[BATCH * NPTS * DIM];  // 8 MB  [pt][c]

// ============================================================================
// k1: smem-staged GEMM. Block = 128 points, 256 threads.
// Xs[67][136] staged once (coalesced); Wt[67][68] = W^T. 8pt x 4out tiles.
// Contraction order c = 0..66 ascending (matches prior passing kernels).
// ============================================================================
#define K1_XP 136
#define K1_WP 68
#define K1_SMEMF (CIN * K1_XP + CIN * K1_WP)   // 9112 + 4556 = 13668 floats

__global__ __launch_bounds__(256) void k1_fg(const float* __restrict__ xyz,
                                             const float* __restrict__ points,
                                             const float* __restrict__ W) {
    extern __shared__ float sm1[];
    float* Xs = sm1;                 // [67][136]
    float* Wt = sm1 + CIN * K1_XP;   // [67][68]  Wt[c][o] = W[o][c]
    const int tid  = threadIdx.x;
    const int base = blockIdx.x * 128;
    const int b    = base >> 12;
    const int n0   = base & (NPTS - 1);

    // stage X: rows 0..63 from points, 64..66 from xyz (coalesced float4 rows)
    for (int t = tid; t < CIN * 32; t += 256) {
        const int row = t >> 5, c4 = t & 31;
        const float* src = (row < 64)
            ? points + ((size_t)(b * DIM + row)) * NPTS + n0 + 4 * c4
            : xyz    + ((size_t)(b * 3 + (row - 64))) * NPTS + n0 + 4 * c4;
        *(float4*)&Xs[row * K1_XP + 4 * c4] = *(const float4*)src;
    }
    // stage W^T
    for (int t = tid; t < 64 * CIN; t += 256) {
        const int c = t >> 6, o = t & 63;
        Wt[c * K1_WP + o] = W[o * CIN + c];
    }
    __syncthreads();

    // pack xyzw for the ball query
    if (tid < 128) {
        float x = Xs[64 * K1_XP + tid];
        float y = Xs[65 * K1_XP + tid];
        float z = Xs[66 * K1_XP + tid];
        float sq = __fadd_rn(__fadd_rn(__fmul_rn(x, x), __fmul_rn(y, y)), __fmul_rn(z, z));
        d_xyzw[base + tid] = make_float4(x, y, z, sq);
    }

    const int to = tid & 15;     // outs 4*to..4*to+3
    const int tp = tid >> 4;     // pts  8*tp..8*tp+7
    float acc[8][4];
#pragma unroll
    for (int i = 0; i < 8; i++)
#pragma unroll
        for (int j = 0; j < 4; j++) acc[i][j] = 0.f;

#pragma unroll 1
    for (int c = 0; c < CIN; c++) {
        float4 xa = *(const float4*)&Xs[c * K1_XP + 8 * tp];
        float4 xb4 = *(const float4*)&Xs[c * K1_XP + 8 * tp + 4];
        float4 w4 = *(const float4*)&Wt[c * K1_WP + 4 * to];
        float xv[8] = {xa.x, xa.y, xa.z, xa.w, xb4.x, xb4.y, xb4.z, xb4.w};
        float wv[4] = {w4.x, w4.y, w4.z, w4.w};
#pragma unroll
        for (int i = 0; i < 8; i++)
#pragma unroll
            for (int j = 0; j < 4; j++)
                acc[i][j] = fmaf(xv[i], wv[j], acc[i][j]);
    }

#pragma unroll
    for (int i = 0; i < 8; i++) {
        const int pt = base + 8 * tp + i;
        *(float4*)&d_FG[(size_t)pt * 64 + 4 * to] =
            make_float4(acc[i][0], acc[i][1], acc[i][2], acc[i][3]);
    }
}

// ============================================================================
// k2: warp per query, software-pipelined scan (128 pts/iter, next tile
// prefetched before ballots). Pad index list to 32 with buf[0].
// Fixed 16x LDG.128 FG-row gather + BN/ReLU epilogue.
// ============================================================================
__global__ __launch_bounds__(64) void k2_ball(const float* __restrict__ W,
                                              const float* __restrict__ bconv,
                                              const float* __restrict__ g,
                                              const float* __restrict__ bt,
                                              const float* __restrict__ rm,
                                              const float* __restrict__ rv) {
    __shared__ int idxbuf[2][KNN];
    const int lane = threadIdx.x & 31;
    const int w    = threadIdx.x >> 5;
    const int gw   = blockIdx.x * 2 + w;
    const int b    = gw >> 12;

    const float4 q = d_xyzw[gw];
    int* buf = idxbuf[w];
    int count = 0;
    const float4* xb = d_xyzw + ((size_t)b << 12);
    const unsigned ltmask = (1u << lane) - 1u;

    float4 p[4];
#pragma unroll
    for (int j = 0; j < 4; j++) p[j] = xb[32 * j + lane];

    for (int base = 0; base < NPTS; base += 128) {
        float4 np[4];
        const int nb = base + 128;
        if (nb < NPTS) {
#pragma unroll
            for (int j = 0; j < 4; j++) np[j] = xb[nb + 32 * j + lane];
        }
#pragma unroll
        for (int j = 0; j < 4; j++) {
            float dot  = fmaf(q.z, p[j].z, fmaf(q.y, p[j].y, __fmul_rn(q.x, p[j].x)));
            float dist = __fsub_rn(__fadd_rn(q.w, p[j].w), __fmul_rn(2.0f, dot));
            unsigned m = __ballot_sync(0xffffffffu, !(dist > 0.04f));
            int pos = count + __popc(m & ltmask);
            if ((m >> lane) & 1u) { if (pos < KNN) buf[pos] = base + 32 * j + lane; }
            count += __popc(m);
        }
        if (count >= KNN) break;
#pragma unroll
        for (int j = 0; j < 4; j++) p[j] = np[j];
    }
    __syncwarp();
    int cnt = min(count, KNN);
    if (lane >= cnt) buf[lane] = buf[0];
    __syncwarp();

    // gather: half-warp h handles rows 2k+h; lane j owns channels 4j..4j+3
    const int h = lane >> 4, j = lane & 15;
    const float* rowbase = d_FG + (((size_t)b << 12) * 64) + 4 * j;
    float mx[4] = {-3.4e38f, -3.4e38f, -3.4e38f, -3.4e38f};
    float mn[4] = { 3.4e38f,  3.4e38f,  3.4e38f,  3.4e38f};
#pragma unroll
    for (int k = 0; k < 16; k++) {
        int i = buf[2 * k + h];
        float4 v = *(const float4*)(rowbase + (size_t)i * 64);
        mx[0] = fmaxf(mx[0], v.x); mn[0] = fminf(mn[0], v.x);
        mx[1] = fmaxf(mx[1], v.y); mn[1] = fminf(mn[1], v.y);
        mx[2] = fmaxf(mx[2], v.z); mn[2] = fminf(mn[2], v.z);
        mx[3] = fmaxf(mx[3], v.w); mn[3] = fminf(mn[3], v.w);
    }
#pragma unroll
    for (int u = 0; u < 4; u++) {
        mx[u] = fmaxf(mx[u], __shfl_xor_sync(0xffffffffu, mx[u], 16));
        mn[u] = fminf(mn[u], __shfl_xor_sync(0xffffffffu, mn[u], 16));
    }

    if (h == 0) {
        const int c = 4 * j;
        float y[4];
#pragma unroll
        for (int u = 0; u < 4; u++) {
            const int cu = c + u;
            float G = fmaf(q.z, __ldg(&W[cu * CIN + 66]),
                      fmaf(q.y, __ldg(&W[cu * CIN + 65]),
                           __fmul_rn(q.x, __ldg(&W[cu * CIN + 64]))));
            float s = __ldg(&g[cu]) * rsqrtf(__ldg(&rv[cu]) + EPSF);
            float C = fmaf(s, __ldg(&bconv[cu]) - __ldg(&rm[cu]), __ldg(&bt[cu]));
            float E = (s >= 0.f) ? mx[u] : mn[u];
            y[u] = fmaxf(0.f, fmaf(s, E - G, C));
        }
        *(float4*)(d_newp + (size_t)gw * 64 + c) = make_float4(y[0], y[1], y[2], y[3]);
    }
}

// ============================================================================
// k3: fused resnet with smem phase-overlay. Block = 64 points, 256 threads.
//   Phase A: Xs[64][68] + W1Ts[64][132] -> GEMM1 -> H kept in REGISTERS.
//   Phase B: Hs[64][132] + W2Ts[128][68] overlay the phase-A region.
// smem = 70.1 KB -> 3 blocks/SM.
// ============================================================================
#define XP    68
#define W1P   132
#define HPD   132
#define W2P   68
#define PB_HS   0                       // Hs at sm+0 (overlays Xs+W1Ts head)
#define PB_W2   (64 * HPD)              // 8448
#define REGION  (PB_W2 + PH * W2P)      // 8448 + 8704 = 17152
#define PA_XS   0
#define PA_W1   (64 * XP)               // 4352  (within REGION)
#define OFF_CST REGION
#define K3_SMEMF (OFF_CST + 384)        // 17536 floats = 70144 B

__global__ __launch_bounds__(256) void k3_fused(
        const float* __restrict__ W1, const float* __restrict__ b1,
        const float* __restrict__ g1, const float* __restrict__ bt1,
        const float* __restrict__ rm1, const float* __restrict__ rv1,
        const float* __restrict__ W2, const float* __restrict__ b2,
        const float* __restrict__ g2, const float* __restrict__ bt2,
        const float* __restrict__ rm2, const float* __restrict__ rv2,
        const float* __restrict__ points, float* __restrict__ out) {
    extern __shared__ float sm[];
    float* A1 = sm + OFF_CST;
    float* C1 = A1 + 128;
    float* A2 = C1 + 128;
    float* C2 = A2 + 64;

    const int tid  = threadIdx.x;
    const int base = blockIdx.x * 64;

    {   // ---- stage phase A ----
        float* Xs   = sm + PA_XS;
        float* W1Ts = sm + PA_W1;
        for (int t = tid; t < 64 * 16; t += 256) {
            int p = t >> 4, qc = t & 15;
            float4 v = *(const float4*)(d_newp + (size_t)(base + p) * 64 + 4 * qc);
            Xs[(4 * qc + 0) * XP + p] = v.x;
            Xs[(4 * qc + 1) * XP + p] = v.y;
            Xs[(4 * qc + 2) * XP + p] = v.z;
            Xs[(4 * qc + 3) * XP + p] = v.w;
        }
        for (int t = tid; t < PH * 64; t += 256) {
            int o = t >> 6, c = t & 63;
            W1Ts[c * W1P + o] = W1[t];
        }
        if (tid < PH) {
            float s = g1[tid] * rsqrtf(rv1[tid] + EPSF);
            A1[tid] = s;
            C1[tid] = fmaf(s, b1[tid] - rm1[tid], bt1[tid]);
        }
        if (tid >= 128 && tid < 192) {
            int d = tid - 128;
            float s = g2[d] * rsqrtf(rv2[d] + EPSF);
            A2[d] = s;
            C2[d] = fmaf(s, b2[d] - rm2[d], bt2[d]);
        }
    }
    __syncthreads();

    const int to = tid & 15;
    const int tp = tid >> 4;
    float acc[4][8];
#pragma unroll
    for (int i = 0; i < 4; i++)
#pragma unroll
        for (int jj = 0; jj < 8; jj++) acc[i][jj] = 0.f;

    {   // ---- Phase A GEMM ----
        const float* Xs   = sm + PA_XS;
        const float* W1Ts = sm + PA_W1;
#pragma unroll 8
        for (int c = 0; c < 64; c++) {
            float4 x  = *(const float4*)&Xs[c * XP + 4 * tp];
            float4 wa = *(const float4*)&W1Ts[c * W1P + 8 * to];
            float4 wb = *(const float4*)&W1Ts[c * W1P + 8 * to + 4];
            float xv[4] = {x.x, x.y, x.z, x.w};
            float wv[8] = {wa.x, wa.y, wa.z, wa.w, wb.x, wb.y, wb.z, wb.w};
#pragma unroll
            for (int i = 0; i < 4; i++)
#pragma unroll
                for (int jj = 0; jj < 8; jj++)
                    acc[i][jj] = fmaf(xv[i], wv[jj], acc[i][jj]);
        }
    }

    // BN + ReLU into registers (H stays resident)
#pragma unroll
    for (int i = 0; i < 4; i++)
#pragma unroll
        for (int jj = 0; jj < 8; jj++) {
            int o = 8 * to + jj;
            acc[i][jj] = fmaxf(0.f, fmaf(A1[o], acc[i][jj], C1[o]));
        }
    __syncthreads();   // all reads of Xs/W1Ts done -> region reusable

    {   // ---- stage phase B (overlay) ----
        float* Hs   = sm + PB_HS;
        float* W2Ts = sm + PB_W2;
#pragma unroll
        for (int i = 0; i < 4; i++) {
            const int p = 4 * tp + i;
            *(float4*)&Hs[p * HPD + 8 * to] =
                make_float4(acc[i][0], acc[i][1], acc[i][2], acc[i][3]);
            *(float4*)&Hs[p * HPD + 8 * to + 4] =
                make_float4(acc[i][4], acc[i][5], acc[i][6], acc[i][7]);
        }
        for (int t = tid; t < 64 * PH; t += 256) {
            int d = t >> 7, o = t & 127;
            W2Ts[o * W2P + d] = W2[t];
        }
    }
    __syncthreads();

    float acc2[4][4];
#pragma unroll
    for (int i = 0; i < 4; i++)
#pragma unroll
        for (int jj = 0; jj < 4; jj++) acc2[i][jj] = 0.f;

    {   // ---- Phase B GEMM ----
        const float* Hs   = sm + PB_HS;
        const float* W2Ts = sm + PB_W2;
#pragma unroll 4
        for (int o = 0; o < PH; o += 4) {
            float4 h0 = *(const float4*)&Hs[(4 * tp + 0) * HPD + o];
            float4 h1 = *(const float4*)&Hs[(4 * tp + 1) * HPD + o];
            float4 h2 = *(const float4*)&Hs[(4 * tp + 2) * HPD + o];
            float4 h3 = *(const float4*)&Hs[(4 * tp + 3) * HPD + o];
            float4 w0 = *(const float4*)&W2Ts[(o + 0) * W2P + 4 * to];
            float4 w1 = *(const float4*)&W2Ts[(o + 1) * W2P + 4 * to];
            float4 w2 = *(const float4*)&W2Ts[(o + 2) * W2P + 4 * to];
            float4 w3 = *(const float4*)&W2Ts[(o + 3) * W2P + 4 * to];
            float hvs[4][4] = {{h0.x, h0.y, h0.z, h0.w}, {h1.x, h1.y, h1.z, h1.w},
                               {h2.x, h2.y, h2.z, h2.w}, {h3.x, h3.y, h3.z, h3.w}};
            float wvs[4][4] = {{w0.x, w0.y, w0.z, w0.w}, {w1.x, w1.y, w1.z, w1.w},
                               {w2.x, w2.y, w2.z, w2.w}, {w3.x, w3.y, w3.z, w3.w}};
#pragma unroll
            for (int i = 0; i < 4; i++)
#pragma unroll
                for (int k = 0; k < 4; k++)
#pragma unroll
                    for (int jj = 0; jj < 4; jj++)
                        acc2[i][jj] = fmaf(hvs[i][k], wvs[k][jj], acc2[i][jj]);
        }
    }

    const int b  = base >> 12;
    const int n0 = (base & (NPTS - 1)) + 4 * tp;
    const float* pin = points + ((size_t)b * 64) * NPTS + n0;
    float* pout = out + (size_t)BATCH * 3 * NPTS + ((size_t)b * 64) * NPTS + n0;
#pragma unroll
    for (int jj = 0; jj < 4; jj++) {
        const int d = 4 * to + jj;
        float4 r = *(const float4*)(pin + (size_t)d * NPTS);
        float4 y;
        y.x = fmaxf(0.f, fmaf(A2[d], acc2[0][jj], C2[d]) + r.x);
        y.y = fmaxf(0.f, fmaf(A2[d], acc2[1][jj], C2[d]) + r.y);
        y.z = fmaxf(0.f, fmaf(A2[d], acc2[2][jj], C2[d]) + r.z);
        y.w = fmaxf(0.f, fmaf(A2[d], acc2[3][jj], C2[d]) + r.w);
        *(float4*)(pout + (size_t)d * NPTS) = y;
    }
}

// ============================================================================
extern "C" void kernel_launch(void* const* d_in, const int* in_sizes, int n_in,
                              void* d_out, int out_size) {
    const float* xyz    = (const float*)d_in[0];
    const float* points = (const float*)d_in[1];
    const float* W      = (const float*)d_in[2];
    const float* bconv  = (const float*)d_in[3];
    const float* g      = (const float*)d_in[4];
    const float* bt     = (const float*)d_in[5];
    const float* rm     = (const float*)d_in[6];
    const float* rv     = (const float*)d_in[7];
    const float* W1     = (const float*)d_in[8];
    const float* b1     = (const float*)d_in[9];
    const float* g1     = (const float*)d_in[10];
    const float* bt1    = (const float*)d_in[11];
    const float* rm1    = (const float*)d_in[12];
    const float* rv1    = (const float*)d_in[13];
    const float* W2     = (const float*)d_in[14];
    const float* b2     = (const float*)d_in[15];
    const float* g2     = (const float*)d_in[16];
    const float* bt2    = (const float*)d_in[17];
    const float* rm2    = (const float*)d_in[18];
    const float* rv2    = (const float*)d_in[19];
    float* out = (float*)d_out;

    cudaMemcpyAsync(out, xyz, (size_t)BATCH * 3 * NPTS * sizeof(float),
                    cudaMemcpyDeviceToDevice, 0);

    const int k1_smem = K1_SMEMF * (int)sizeof(float);
    cudaFuncSetAttribute(k1_fg, cudaFuncAttributeMaxDynamicSharedMemorySize, k1_smem);
    k1_fg<<<(BATCH * NPTS) / 128, 256, k1_smem>>>(xyz, points, W);

    k2_ball<<<(BATCH * NPTS) / 2, 64>>>(W, bconv, g, bt, rm, rv);

    const int k3_smem = K3_SMEMF * (int)sizeof(float);
    cudaFuncSetAttribute(k3_fused, cudaFuncAttributeMaxDynamicSharedMemorySize, k3_smem);
    k3_fused<<<(BATCH * NPTS) / 64, 256, k3_smem>>>(W1, b1, g1, bt1, rm1, rv1,
                                                    W2, b2, g2, bt2, rm2, rv2,
                                                    points, out);
    (void)in_sizes; (void)n_in; (void)out_size;
}